// round 15
// baseline (speedup 1.0000x reference)
#include <cuda_runtime.h>
#include <cuda_fp16.h>
#include <cuda_bf16.h>
#include <cstdint>

#define N_NODES 100000
#define N_PAD   100096            // multiple of 128; rows N_NODES..N_PAD-1 stay zero forever
#define N_EDGES 1600000
#define IN_DIM 64
#define HID_DIM 128
#define EMB_DIM 64
#define SLOT_CAP 64               // P(deg > 64) ~ 1e-19 for Poisson(16)

// ---- scratch (device globals; no allocation allowed) ----
// g_cnt starts zero (static init) and is re-zeroed by k_gather2 each replay.
__device__ int   g_cnt[N_NODES];
__device__ int   g_slot[N_NODES * SLOT_CAP];
__device__ float g_dinv[N_PAD];               // pad entries stay 0 -> y[pad] = 0
__device__ __align__(16) __half g_w1h[IN_DIM * HID_DIM];
__device__ __align__(16) __half g_w2h[HID_DIM * EMB_DIM];
__device__ __align__(16) __half g_xsh [N_PAD * IN_DIM];   // x * dinv[row] (fp16); pad rows = 0
__device__ __align__(16) __half g_aggh[N_PAD * IN_DIM];   // dinv[c] * aggregated input
__device__ __align__(16) __half g_yh  [N_PAD * EMB_DIM];  // (h @ W2) * dinv[row]; pad rows = 0

union PK2 { __half2 h[2]; uint2 u; };

// ---------------- fill: counts + slot placement in ONE atomic pass (2 edges/thread) ----------------
__global__ void k_fill(const int* __restrict__ ei) {
    int e = (blockIdx.x * blockDim.x + threadIdx.x) * 2;
    if (e >= N_EDGES) return;
    int2 rr = *(const int2*)&ei[e];
    int2 cc = *(const int2*)&ei[N_EDGES + e];
    if ((unsigned)rr.x < N_NODES && (unsigned)cc.x < N_NODES) {
        int pos = atomicAdd(&g_cnt[cc.x], 1);
        if (pos < SLOT_CAP) g_slot[cc.x * SLOT_CAP + pos] = rr.x;
    }
    if ((unsigned)rr.y < N_NODES && (unsigned)cc.y < N_NODES) {
        int pos = atomicAdd(&g_cnt[cc.y], 1);
        if (pos < SLOT_CAP) g_slot[cc.y * SLOT_CAP + pos] = rr.y;
    }
}

// ---------------- xs = x * dinv[row] (fp32 -> fp16), dinv inline; also converts weights ----------------
__global__ void k_xs(const float* __restrict__ x,
                     const float* __restrict__ W1, const float* __restrict__ W2) {
    int i = blockIdx.x * blockDim.x + threadIdx.x;   // float4 chunk index
    if (i < IN_DIM * HID_DIM) g_w1h[i] = __float2half(W1[i]);
    if (i < HID_DIM * EMB_DIM) g_w2h[i] = __float2half(W2[i]);
    if (i >= N_NODES * (IN_DIM / 4)) return;
    int node = i >> 4;
    float s = rsqrtf((float)g_cnt[node] + 1.0f);
    if ((i & 15) == 0) g_dinv[node] = s;
    float4 v = *(const float4*)&x[i * 4];
    PK2 p;
    p.h[0] = __floats2half2_rn(v.x * s, v.y * s);
    p.h[1] = __floats2half2_rn(v.z * s, v.w * s);
    *(uint2*)&g_xsh[i * 4] = p.u;
}

// ---- gather core: fixed trip count K quad-iterations; each 16-lane half
//      sums 4 neighbors per iteration via an HADD2 tree, then one fp32 convert+add.
template<int K>
__device__ __forceinline__ void gather_core(const uint2* __restrict__ tab, int myidx,
                                            unsigned l, int h,
                                            float2& acc0, float2& acc1) {
    #pragma unroll
    for (int k = 0; k < K; k++) {
        int j = k * 8 + h * 4;
        int r0 = __shfl_sync(0xffffffffu, myidx, j);
        int r1 = __shfl_sync(0xffffffffu, myidx, j + 1);
        int r2 = __shfl_sync(0xffffffffu, myidx, j + 2);
        int r3 = __shfl_sync(0xffffffffu, myidx, j + 3);
        uint2 u0 = tab[(unsigned)r0 * 16u + l];
        uint2 u1 = tab[(unsigned)r1 * 16u + l];
        uint2 u2 = tab[(unsigned)r2 * 16u + l];
        uint2 u3 = tab[(unsigned)r3 * 16u + l];
        __half2 x01 = __hadd2(*(__half2*)&u0.x, *(__half2*)&u1.x);
        __half2 x23 = __hadd2(*(__half2*)&u2.x, *(__half2*)&u3.x);
        __half2 y01 = __hadd2(*(__half2*)&u0.y, *(__half2*)&u1.y);
        __half2 y23 = __hadd2(*(__half2*)&u2.y, *(__half2*)&u3.y);
        float2 f0 = __half22float2(__hadd2(x01, x23));
        float2 f1 = __half22float2(__hadd2(y01, y23));
        acc0.x += f0.x; acc0.y += f0.y; acc1.x += f1.x; acc1.y += f1.y;
    }
}

__device__ __forceinline__ void gather_node(const uint2* __restrict__ tab, int node,
                                            int lane, float2& acc0, float2& acc1) {
    unsigned l = lane & 15;
    int h = lane >> 4;

    int cnt = g_cnt[node];
    if (cnt > SLOT_CAP) cnt = SLOT_CAP;
    const int* slots = &g_slot[node * SLOT_CAP];
    int myidx = N_NODES;                        // dummy -> zero row
    if (lane < cnt) myidx = slots[lane];
    else if (lane == cnt) myidx = node;         // embed self (only if cnt < 32)

    int total = (cnt < 32) ? cnt + 1 : 32;
    int lim8 = (total + 7) & ~7;                // 8/16/24/32

    acc0 = make_float2(0.f, 0.f);
    acc1 = make_float2(0.f, 0.f);
    switch (lim8 >> 3) {
        case 1: gather_core<1>(tab, myidx, l, h, acc0, acc1); break;
        case 2: gather_core<2>(tab, myidx, l, h, acc0, acc1); break;
        case 3: gather_core<3>(tab, myidx, l, h, acc0, acc1); break;
        default: gather_core<4>(tab, myidx, l, h, acc0, acc1); break;
    }

    if (cnt >= 32) {                            // rare (P ~ 2e-4): scalar tail + self
        for (int i2 = 32 + h; i2 < cnt; i2 += 2) {
            uint2 u = tab[(unsigned)slots[i2] * 16u + l];
            float2 f0 = __half22float2(*(__half2*)&u.x);
            float2 f1 = __half22float2(*(__half2*)&u.y);
            acc0.x += f0.x; acc0.y += f0.y; acc1.x += f1.x; acc1.y += f1.y;
        }
        uint2 u = tab[(unsigned)node * 16u + l];
        if (h == 0) {
            float2 f0 = __half22float2(*(__half2*)&u.x);
            float2 f1 = __half22float2(*(__half2*)&u.y);
            acc0.x += f0.x; acc0.y += f0.y; acc1.x += f1.x; acc1.y += f1.y;
        }
    }

    acc0.x += __shfl_xor_sync(0xffffffffu, acc0.x, 16);
    acc0.y += __shfl_xor_sync(0xffffffffu, acc0.y, 16);
    acc1.x += __shfl_xor_sync(0xffffffffu, acc1.x, 16);
    acc1.y += __shfl_xor_sync(0xffffffffu, acc1.y, 16);
}

// ---------------- gather1: aggh[c] = dinv[c]*(xs[c] + sum xs[r]) ----------------
__global__ __launch_bounds__(256) void k_gather1() {
    int warp = threadIdx.x >> 5;
    int lane = threadIdx.x & 31;
    int node = blockIdx.x * 8 + warp;
    if (node >= N_NODES) return;

    float2 acc0, acc1;
    gather_node((const uint2*)g_xsh, node, lane, acc0, acc1);

    if ((lane >> 4) == 0) {
        float s = g_dinv[node];
        PK2 p;
        p.h[0] = __floats2half2_rn(acc0.x * s, acc0.y * s);
        p.h[1] = __floats2half2_rn(acc1.x * s, acc1.y * s);
        *(uint2*)&g_aggh[(unsigned)node * IN_DIM + (lane & 15) * 4] = p.u;
    }
}

// ---------------- fused GEMM, register handoff ----------------
// 128-row tile, 8 warps; each warp owns 16 rows.
// Phase1: warp computes h(16 x 128) into d1[16][4] (full HID_DIM per warp).
// Convert: relu(d1 + b1) -> ah[8][4] half2 A-fragments (C-frag layout == A-frag layout).
// Phase2: y(16 x 64) = ah @ W2, scaled by dinv, straight to g_yh. No Hs smem roundtrip.
__global__ __launch_bounds__(256) void k_gemm12(const float* __restrict__ b1) {
    __shared__ __align__(16) __half S[17920];   // 35840 bytes
    __half* As  = S;                            // 128*72 = 9216 halves (phase1)
    __half* Bs1 = S + 9216;                     // 64*136 = 8704 halves
    __half* Bs2 = S;                            // 128*72 = 9216 halves (aliases As)

    int tid = threadIdx.x;
    int row0 = blockIdx.x * 128;
    int warp = tid >> 5, lane = tid & 31;

    #pragma unroll
    for (int i = tid; i < 1024; i += 256) {          // As: 128x64
        int row = i >> 3, c = (i & 7) * 8;
        *(uint4*)&As[row * 72 + c] = *(const uint4*)&g_aggh[(size_t)(row0 + row) * IN_DIM + c];
    }
    #pragma unroll
    for (int i = tid; i < 1024; i += 256) {          // Bs1: 64x128 (W1)
        int k = i >> 4, n = (i & 15) * 8;
        *(uint4*)&Bs1[k * 136 + n] = *(const uint4*)&g_w1h[k * 128 + n];
    }
    __syncthreads();

    // ---- phase 1: rows warp*16..+15, N=128, K=64
    float d1[16][4] = {};
    #pragma unroll
    for (int ks = 0; ks < 4; ks++) {
        int k0 = ks * 16;
        uint32_t a[4];
        uint32_t aaddr = (uint32_t)__cvta_generic_to_shared(
            &As[(warp * 16 + (lane & 15)) * 72 + k0 + (lane >> 4) * 8]);
        asm volatile("ldmatrix.sync.aligned.m8n8.x4.shared.b16 {%0,%1,%2,%3}, [%4];"
                     : "=r"(a[0]), "=r"(a[1]), "=r"(a[2]), "=r"(a[3]) : "r"(aaddr));
        #pragma unroll
        for (int ng = 0; ng < 8; ng++) {
            int n0 = ng * 16;
            uint32_t b[4];
            uint32_t baddr = (uint32_t)__cvta_generic_to_shared(
                &Bs1[(k0 + (lane & 15)) * 136 + n0 + (lane >> 4) * 8]);
            asm volatile("ldmatrix.sync.aligned.m8n8.x4.trans.shared.b16 {%0,%1,%2,%3}, [%4];"
                         : "=r"(b[0]), "=r"(b[1]), "=r"(b[2]), "=r"(b[3]) : "r"(baddr));
            #pragma unroll
            for (int p = 0; p < 2; p++) {
                float* dd = d1[ng * 2 + p];
                asm volatile("mma.sync.aligned.m16n8k16.row.col.f32.f16.f16.f32 "
                             "{%0,%1,%2,%3}, {%4,%5,%6,%7}, {%8,%9}, {%0,%1,%2,%3};"
                             : "+f"(dd[0]), "+f"(dd[1]), "+f"(dd[2]), "+f"(dd[3])
                             : "r"(a[0]), "r"(a[1]), "r"(a[2]), "r"(a[3]),
                               "r"(b[p * 2]), "r"(b[p * 2 + 1]));
            }
        }
    }

    // ---- register handoff: relu(d1 + b1) -> phase2 A fragments (half2)
    // C-frag (row=lane>>2 / +8, col=2*(lane&3) / +1) == A-frag m16n8k16 mapping.
    uint32_t ah[8][4];
    #pragma unroll
    for (int ks = 0; ks < 8; ks++) {
        int c0 = ks * 16 + (lane & 3) * 2;
        float2 bb0 = *(const float2*)&b1[c0];
        float2 bb1 = *(const float2*)&b1[c0 + 8];
        float* p0 = d1[ks * 2];
        float* p1 = d1[ks * 2 + 1];
        __half2 v;
        v = __floats2half2_rn(fmaxf(p0[0] + bb0.x, 0.f), fmaxf(p0[1] + bb0.y, 0.f));
        ah[ks][0] = *(uint32_t*)&v;
        v = __floats2half2_rn(fmaxf(p0[2] + bb0.x, 0.f), fmaxf(p0[3] + bb0.y, 0.f));
        ah[ks][1] = *(uint32_t*)&v;
        v = __floats2half2_rn(fmaxf(p1[0] + bb1.x, 0.f), fmaxf(p1[1] + bb1.y, 0.f));
        ah[ks][2] = *(uint32_t*)&v;
        v = __floats2half2_rn(fmaxf(p1[2] + bb1.x, 0.f), fmaxf(p1[3] + bb1.y, 0.f));
        ah[ks][3] = *(uint32_t*)&v;
    }

    __syncthreads();                                  // everyone done reading As
    #pragma unroll
    for (int i = tid; i < 1024; i += 256) {          // Bs2: 128x64 (W2), aliases As
        int k = i >> 3, n = (i & 7) * 8;
        *(uint4*)&Bs2[k * 72 + n] = *(const uint4*)&g_w2h[k * 64 + n];
    }
    __syncthreads();

    // ---- phase 2: rows warp*16..+15, N=64, K=128; A from registers
    float d2[8][4] = {};
    #pragma unroll
    for (int ks = 0; ks < 8; ks++) {
        int k0 = ks * 16;
        #pragma unroll
        for (int ng = 0; ng < 4; ng++) {
            int n0 = ng * 16;
            uint32_t b[4];
            uint32_t baddr = (uint32_t)__cvta_generic_to_shared(
                &Bs2[(k0 + (lane & 15)) * 72 + n0 + (lane >> 4) * 8]);
            asm volatile("ldmatrix.sync.aligned.m8n8.x4.trans.shared.b16 {%0,%1,%2,%3}, [%4];"
                         : "=r"(b[0]), "=r"(b[1]), "=r"(b[2]), "=r"(b[3]) : "r"(baddr));
            #pragma unroll
            for (int p = 0; p < 2; p++) {
                float* dd = d2[ng * 2 + p];
                asm volatile("mma.sync.aligned.m16n8k16.row.col.f32.f16.f16.f32 "
                             "{%0,%1,%2,%3}, {%4,%5,%6,%7}, {%8,%9}, {%0,%1,%2,%3};"
                             : "+f"(dd[0]), "+f"(dd[1]), "+f"(dd[2]), "+f"(dd[3])
                             : "r"(ah[ks][0]), "r"(ah[ks][1]), "r"(ah[ks][2]), "r"(ah[ks][3]),
                               "r"(b[p * 2]), "r"(b[p * 2 + 1]));
            }
        }
    }

    int r = row0 + warp * 16 + (lane >> 2);
    float s0 = g_dinv[r], s1 = g_dinv[r + 8];        // pad rows: dinv=0 -> y=0
    #pragma unroll
    for (int nf = 0; nf < 8; nf++) {
        int c = nf * 8 + (lane & 3) * 2;
        float* dd = d2[nf];
        *(__half2*)&g_yh[(size_t)r * EMB_DIM + c] =
            __floats2half2_rn(dd[0] * s0, dd[1] * s0);
        *(__half2*)&g_yh[(size_t)(r + 8) * EMB_DIM + c] =
            __floats2half2_rn(dd[2] * s1, dd[3] * s1);
    }
}

// ---------------- gather2 + finalize: out = dinv[c]*(y[c] + sum y[r]) + b2 ----------------
// Also re-zeroes g_cnt[node] for the next graph replay (last reader).
__global__ __launch_bounds__(256) void k_gather2(const float* __restrict__ b2,
                                                 float* __restrict__ out) {
    int warp = threadIdx.x >> 5;
    int lane = threadIdx.x & 31;
    int node = blockIdx.x * 8 + warp;
    if (node >= N_NODES) return;

    float2 acc0, acc1;
    gather_node((const uint2*)g_yh, node, lane, acc0, acc1);

    if (lane == 0) g_cnt[node] = 0;   // reset for next replay (after gather_node read it)

    if ((lane >> 4) == 0) {
        unsigned l = lane & 15;
        float s = g_dinv[node];
        float4 bv = *(const float4*)&b2[l * 4];
        float4 o;
        o.x = acc0.x * s + bv.x;
        o.y = acc0.y * s + bv.y;
        o.z = acc1.x * s + bv.z;
        o.w = acc1.y * s + bv.w;
        *(float4*)&out[(unsigned)node * EMB_DIM + l * 4] = o;
    }
}

extern "C" void kernel_launch(void* const* d_in, const int* in_sizes, int n_in,
                              void* d_out, int out_size) {
    const float* x  = (const float*)d_in[0];
    const int*   ei = (const int*)d_in[1];
    const float* W1 = (const float*)d_in[2];
    const float* b1 = (const float*)d_in[3];
    const float* W2 = (const float*)d_in[4];
    const float* b2 = (const float*)d_in[5];
    float* out = (float*)d_out;

    k_fill<<<(N_EDGES / 2 + 255) / 256, 256>>>(ei);
    k_xs<<<(N_NODES * (IN_DIM / 4) + 255) / 256, 256>>>(x, W1, W2);
    k_gather1<<<(N_NODES + 7) / 8, 256>>>();
    k_gemm12<<<N_PAD / 128, 256>>>(b1);
    k_gather2<<<(N_NODES + 7) / 8, 256>>>(b2, out);
}

// round 16
// speedup vs baseline: 1.0216x; 1.0216x over previous
#include <cuda_runtime.h>
#include <cuda_fp16.h>
#include <cuda_bf16.h>
#include <cstdint>

#define N_NODES 100000
#define N_PAD   100096            // multiple of 128; rows N_NODES..N_PAD-1 stay zero forever
#define N_EDGES 1600000
#define IN_DIM 64
#define HID_DIM 128
#define EMB_DIM 64
#define SLOT_CAP 64               // P(deg > 64) ~ 1e-19 for Poisson(16)

// ---- scratch (device globals; no allocation allowed) ----
// g_cnt starts zero (static init) and is re-zeroed by k_gather2 each replay.
__device__ int   g_cnt[N_NODES];
__device__ int   g_slot[N_NODES * SLOT_CAP];
__device__ float g_dinv[N_PAD];               // pad entries stay 0 -> y[pad] = 0
__device__ __align__(16) __half g_w1h[IN_DIM * HID_DIM];
__device__ __align__(16) __half g_w2h[HID_DIM * EMB_DIM];
__device__ __align__(16) __half g_xsh [N_PAD * IN_DIM];   // x * dinv[row] (fp16); pad rows = 0
__device__ __align__(16) __half g_aggh[N_PAD * IN_DIM];   // dinv[c] * aggregated input
__device__ __align__(16) __half g_yh  [N_PAD * EMB_DIM];  // (h @ W2) * dinv[row]; pad rows = 0

union PK2 { __half2 h[2]; uint2 u; };

// ---------------- fill: counts + slot placement in ONE atomic pass (2 edges/thread) ----------------
__global__ void k_fill(const int* __restrict__ ei) {
    int e = (blockIdx.x * blockDim.x + threadIdx.x) * 2;
    if (e < N_EDGES) {
        int2 rr = *(const int2*)&ei[e];
        int2 cc = *(const int2*)&ei[N_EDGES + e];
        if ((unsigned)rr.x < N_NODES && (unsigned)cc.x < N_NODES) {
            int pos = atomicAdd(&g_cnt[cc.x], 1);
            if (pos < SLOT_CAP) g_slot[cc.x * SLOT_CAP + pos] = rr.x;
        }
        if ((unsigned)rr.y < N_NODES && (unsigned)cc.y < N_NODES) {
            int pos = atomicAdd(&g_cnt[cc.y], 1);
            if (pos < SLOT_CAP) g_slot[cc.y * SLOT_CAP + pos] = rr.y;
        }
    }
    cudaTriggerProgrammaticLaunchCompletion();
}

// ---------------- xs = x * dinv[row] (fp32 -> fp16), dinv inline; also converts weights ----------------
__global__ void k_xs(const float* __restrict__ x,
                     const float* __restrict__ W1, const float* __restrict__ W2) {
    int i = blockIdx.x * blockDim.x + threadIdx.x;   // float4 chunk index
    // prelude: weight conversion reads only harness inputs -> safe before sync
    if (i < IN_DIM * HID_DIM) g_w1h[i] = __float2half(W1[i]);
    if (i < HID_DIM * EMB_DIM) g_w2h[i] = __float2half(W2[i]);
    cudaGridDependencySynchronize();                 // wait k_fill (g_cnt)
    if (i < N_NODES * (IN_DIM / 4)) {
        int node = i >> 4;
        float s = rsqrtf((float)g_cnt[node] + 1.0f);
        if ((i & 15) == 0) g_dinv[node] = s;
        float4 v = *(const float4*)&x[i * 4];
        PK2 p;
        p.h[0] = __floats2half2_rn(v.x * s, v.y * s);
        p.h[1] = __floats2half2_rn(v.z * s, v.w * s);
        *(uint2*)&g_xsh[i * 4] = p.u;
    }
    cudaTriggerProgrammaticLaunchCompletion();
}

// ---- gather core: fixed trip count K; each 16-lane half sums 2 neighbors
//      per iteration via HADD2 (4 neighbors/warp-iter -> granularity 4).
template<int K>
__device__ __forceinline__ void gather_core(const uint2* __restrict__ tab, int myidx,
                                            unsigned l, int h,
                                            float2& acc0, float2& acc1) {
    #pragma unroll
    for (int k = 0; k < K; k++) {
        int j = k * 4 + h * 2;
        int r0 = __shfl_sync(0xffffffffu, myidx, j);
        int r1 = __shfl_sync(0xffffffffu, myidx, j + 1);
        uint2 u0 = tab[(unsigned)r0 * 16u + l];
        uint2 u1 = tab[(unsigned)r1 * 16u + l];
        __half2 s0 = __hadd2(*(__half2*)&u0.x, *(__half2*)&u1.x);
        __half2 s1 = __hadd2(*(__half2*)&u0.y, *(__half2*)&u1.y);
        float2 f0 = __half22float2(s0);
        float2 f1 = __half22float2(s1);
        acc0.x += f0.x; acc0.y += f0.y; acc1.x += f1.x; acc1.y += f1.y;
    }
}

__device__ __forceinline__ void gather_node(const uint2* __restrict__ tab, int node,
                                            int lane, float2& acc0, float2& acc1) {
    unsigned l = lane & 15;
    int h = lane >> 4;

    int cnt = g_cnt[node];
    if (cnt > SLOT_CAP) cnt = SLOT_CAP;
    const int* slots = &g_slot[node * SLOT_CAP];
    int myidx = N_NODES;                        // dummy -> zero row
    if (lane < cnt) myidx = slots[lane];
    else if (lane == cnt) myidx = node;         // embed self (only if cnt < 32)

    int total = (cnt < 32) ? cnt + 1 : 32;
    int q4 = (total + 3) >> 2;                  // 1..8  (granularity 4)

    acc0 = make_float2(0.f, 0.f);
    acc1 = make_float2(0.f, 0.f);
    switch (q4) {
        case 1: gather_core<1>(tab, myidx, l, h, acc0, acc1); break;
        case 2: gather_core<2>(tab, myidx, l, h, acc0, acc1); break;
        case 3: gather_core<3>(tab, myidx, l, h, acc0, acc1); break;
        case 4: gather_core<4>(tab, myidx, l, h, acc0, acc1); break;
        case 5: gather_core<5>(tab, myidx, l, h, acc0, acc1); break;
        case 6: gather_core<6>(tab, myidx, l, h, acc0, acc1); break;
        case 7: gather_core<7>(tab, myidx, l, h, acc0, acc1); break;
        default: gather_core<8>(tab, myidx, l, h, acc0, acc1); break;
    }

    if (cnt >= 32) {                            // rare (P ~ 2e-4): scalar tail + self
        for (int i2 = 32 + h; i2 < cnt; i2 += 2) {
            uint2 u = tab[(unsigned)slots[i2] * 16u + l];
            float2 f0 = __half22float2(*(__half2*)&u.x);
            float2 f1 = __half22float2(*(__half2*)&u.y);
            acc0.x += f0.x; acc0.y += f0.y; acc1.x += f1.x; acc1.y += f1.y;
        }
        uint2 u = tab[(unsigned)node * 16u + l];
        if (h == 0) {
            float2 f0 = __half22float2(*(__half2*)&u.x);
            float2 f1 = __half22float2(*(__half2*)&u.y);
            acc0.x += f0.x; acc0.y += f0.y; acc1.x += f1.x; acc1.y += f1.y;
        }
    }

    acc0.x += __shfl_xor_sync(0xffffffffu, acc0.x, 16);
    acc0.y += __shfl_xor_sync(0xffffffffu, acc0.y, 16);
    acc1.x += __shfl_xor_sync(0xffffffffu, acc1.x, 16);
    acc1.y += __shfl_xor_sync(0xffffffffu, acc1.y, 16);
}

// ---------------- gather1: aggh[c] = dinv[c]*(xs[c] + sum xs[r]) ----------------
__global__ __launch_bounds__(256) void k_gather1() {
    cudaGridDependencySynchronize();                 // wait k_xs (g_xsh, g_dinv)
    int warp = threadIdx.x >> 5;
    int lane = threadIdx.x & 31;
    int node = blockIdx.x * 8 + warp;
    if (node < N_NODES) {
        float2 acc0, acc1;
        gather_node((const uint2*)g_xsh, node, lane, acc0, acc1);

        if ((lane >> 4) == 0) {
            float s = g_dinv[node];
            PK2 p;
            p.h[0] = __floats2half2_rn(acc0.x * s, acc0.y * s);
            p.h[1] = __floats2half2_rn(acc1.x * s, acc1.y * s);
            *(uint2*)&g_aggh[(unsigned)node * IN_DIM + (lane & 15) * 4] = p.u;
        }
    }
    cudaTriggerProgrammaticLaunchCompletion();
}

// ---------------- fused GEMM: h = relu(aggh@W1 + b1) (smem); y = (h@W2)*dinv ----------------
// 64-row tile. Phase1: 64x128, K=64 (warp 32x32). Phase2: 64x64, K=128 (warp 16x32).
// smem union: phase1 [As 64x72 | Bs1 64x136], phase2 [Hs 64x136 | Bs2 128x72] = 35840 B.
__global__ __launch_bounds__(256) void k_gemm12(const float* __restrict__ b1) {
    __shared__ __align__(16) __half S[17920];   // 35840 bytes
    __half* As  = S;                            // 64*72   = 4608 halves
    __half* Bs1 = S + 4608;                     // 64*136  = 8704 halves
    __half* Hs  = S;                            // 64*136  = 8704 halves
    __half* Bs2 = S + 8704;                     // 128*72  = 9216 halves

    int tid = threadIdx.x;
    int row0 = blockIdx.x * 64;
    int warp = tid >> 5, lane = tid & 31;

    cudaGridDependencySynchronize();                 // wait k_gather1 (g_aggh)

    // phase-1 loads
    #pragma unroll
    for (int i = tid; i < 512; i += 256) {           // As: 64x64
        int row = i >> 3, c = (i & 7) * 8;
        *(uint4*)&As[row * 72 + c] = *(const uint4*)&g_aggh[(size_t)(row0 + row) * IN_DIM + c];
    }
    #pragma unroll
    for (int i = tid; i < 1024; i += 256) {          // Bs1: 64x128 (W1)
        int k = i >> 4, n = (i & 15) * 8;
        *(uint4*)&Bs1[k * 136 + n] = *(const uint4*)&g_w1h[k * 128 + n];
    }
    __syncthreads();

    // ---- phase 1 mainloop: 64x128, K=64; warps 2M x 4N, warp tile 32x32
    int wm = warp >> 2, wn = warp & 3;
    float d1[2][4][4] = {};
    #pragma unroll
    for (int ks = 0; ks < 4; ks++) {
        int k0 = ks * 16;
        uint32_t a[2][4];
        #pragma unroll
        for (int mf = 0; mf < 2; mf++) {
            uint32_t aaddr = (uint32_t)__cvta_generic_to_shared(
                &As[(wm * 32 + mf * 16 + (lane & 15)) * 72 + k0 + (lane >> 4) * 8]);
            asm volatile("ldmatrix.sync.aligned.m8n8.x4.shared.b16 {%0,%1,%2,%3}, [%4];"
                         : "=r"(a[mf][0]), "=r"(a[mf][1]), "=r"(a[mf][2]), "=r"(a[mf][3])
                         : "r"(aaddr));
        }
        #pragma unroll
        for (int nfl = 0; nfl < 2; nfl++) {
            int n0 = wn * 32 + nfl * 16;
            uint32_t b[4];
            uint32_t baddr = (uint32_t)__cvta_generic_to_shared(
                &Bs1[(k0 + (lane & 15)) * 136 + n0 + (lane >> 4) * 8]);
            asm volatile("ldmatrix.sync.aligned.m8n8.x4.trans.shared.b16 {%0,%1,%2,%3}, [%4];"
                         : "=r"(b[0]), "=r"(b[1]), "=r"(b[2]), "=r"(b[3]) : "r"(baddr));
            #pragma unroll
            for (int mf = 0; mf < 2; mf++) {
                #pragma unroll
                for (int p = 0; p < 2; p++) {
                    float* dd = d1[mf][nfl * 2 + p];
                    asm volatile("mma.sync.aligned.m16n8k16.row.col.f32.f16.f16.f32 "
                                 "{%0,%1,%2,%3}, {%4,%5,%6,%7}, {%8,%9}, {%0,%1,%2,%3};"
                                 : "+f"(dd[0]), "+f"(dd[1]), "+f"(dd[2]), "+f"(dd[3])
                                 : "r"(a[mf][0]), "r"(a[mf][1]), "r"(a[mf][2]), "r"(a[mf][3]),
                                   "r"(b[p * 2]), "r"(b[p * 2 + 1]));
                }
            }
        }
    }
    __syncthreads();   // done reading As/Bs1; smem about to be repurposed

    // epilogue 1: h -> Hs (relu + b1), and load Bs2 (W2)
    #pragma unroll
    for (int mf = 0; mf < 2; mf++) {
        int r = wm * 32 + mf * 16 + (lane >> 2);
        #pragma unroll
        for (int nf = 0; nf < 4; nf++) {
            int c = wn * 32 + nf * 8 + (lane & 3) * 2;
            float2 bb = *(const float2*)&b1[c];
            float* dd = d1[mf][nf];
            *(__half2*)&Hs[r * 136 + c] =
                __floats2half2_rn(fmaxf(dd[0] + bb.x, 0.f), fmaxf(dd[1] + bb.y, 0.f));
            *(__half2*)&Hs[(r + 8) * 136 + c] =
                __floats2half2_rn(fmaxf(dd[2] + bb.x, 0.f), fmaxf(dd[3] + bb.y, 0.f));
        }
    }
    #pragma unroll
    for (int i = tid; i < 1024; i += 256) {          // Bs2: 128x64 (W2)
        int k = i >> 3, n = (i & 7) * 8;
        *(uint4*)&Bs2[k * 72 + n] = *(const uint4*)&g_w2h[k * 64 + n];
    }
    __syncthreads();

    // ---- phase 2 mainloop: 64x64, K=128; warps 4M x 2N, warp tile 16x32
    int wm2 = warp >> 1, wn2 = warp & 1;
    float d2[4][4] = {};
    #pragma unroll
    for (int ks = 0; ks < 8; ks++) {
        int k0 = ks * 16;
        uint32_t a[4];
        uint32_t aaddr = (uint32_t)__cvta_generic_to_shared(
            &Hs[(wm2 * 16 + (lane & 15)) * 136 + k0 + (lane >> 4) * 8]);
        asm volatile("ldmatrix.sync.aligned.m8n8.x4.shared.b16 {%0,%1,%2,%3}, [%4];"
                     : "=r"(a[0]), "=r"(a[1]), "=r"(a[2]), "=r"(a[3]) : "r"(aaddr));
        #pragma unroll
        for (int nfl = 0; nfl < 2; nfl++) {
            int n0 = wn2 * 32 + nfl * 16;
            uint32_t b[4];
            uint32_t baddr = (uint32_t)__cvta_generic_to_shared(
                &Bs2[(k0 + (lane & 15)) * 72 + n0 + (lane >> 4) * 8]);
            asm volatile("ldmatrix.sync.aligned.m8n8.x4.trans.shared.b16 {%0,%1,%2,%3}, [%4];"
                         : "=r"(b[0]), "=r"(b[1]), "=r"(b[2]), "=r"(b[3]) : "r"(baddr));
            #pragma unroll
            for (int p = 0; p < 2; p++) {
                float* dd = d2[nfl * 2 + p];
                asm volatile("mma.sync.aligned.m16n8k16.row.col.f32.f16.f16.f32 "
                             "{%0,%1,%2,%3}, {%4,%5,%6,%7}, {%8,%9}, {%0,%1,%2,%3};"
                             : "+f"(dd[0]), "+f"(dd[1]), "+f"(dd[2]), "+f"(dd[3])
                             : "r"(a[0]), "r"(a[1]), "r"(a[2]), "r"(a[3]),
                               "r"(b[p * 2]), "r"(b[p * 2 + 1]));
            }
        }
    }

    int r = row0 + wm2 * 16 + (lane >> 2);
    float s0 = g_dinv[r], s1 = g_dinv[r + 8];
    #pragma unroll
    for (int nf = 0; nf < 4; nf++) {
        int c = wn2 * 32 + nf * 8 + (lane & 3) * 2;
        float* dd = d2[nf];
        *(__half2*)&g_yh[(size_t)r * EMB_DIM + c] =
            __floats2half2_rn(dd[0] * s0, dd[1] * s0);
        *(__half2*)&g_yh[(size_t)(r + 8) * EMB_DIM + c] =
            __floats2half2_rn(dd[2] * s1, dd[3] * s1);
    }
    cudaTriggerProgrammaticLaunchCompletion();
}

// ---------------- gather2 + finalize: out = dinv[c]*(y[c] + sum y[r]) + b2 ----------------
// Also re-zeroes g_cnt[node] for the next graph replay (last reader).
__global__ __launch_bounds__(256) void k_gather2(const float* __restrict__ b2,
                                                 float* __restrict__ out) {
    cudaGridDependencySynchronize();                 // wait k_gemm12 (g_yh)
    int warp = threadIdx.x >> 5;
    int lane = threadIdx.x & 31;
    int node = blockIdx.x * 8 + warp;
    if (node >= N_NODES) return;

    float2 acc0, acc1;
    gather_node((const uint2*)g_yh, node, lane, acc0, acc1);

    if (lane == 0) g_cnt[node] = 0;   // reset for next replay (after gather_node read it)

    if ((lane >> 4) == 0) {
        unsigned l = lane & 15;
        float s = g_dinv[node];
        float4 bv = *(const float4*)&b2[l * 4];
        float4 o;
        o.x = acc0.x * s + bv.x;
        o.y = acc0.y * s + bv.y;
        o.z = acc1.x * s + bv.z;
        o.w = acc1.y * s + bv.w;
        *(float4*)&out[(unsigned)node * EMB_DIM + l * 4] = o;
    }
}

extern "C" void kernel_launch(void* const* d_in, const int* in_sizes, int n_in,
                              void* d_out, int out_size) {
    const float* x  = (const float*)d_in[0];
    const int*   ei = (const int*)d_in[1];
    const float* W1 = (const float*)d_in[2];
    const float* b1 = (const float*)d_in[3];
    const float* W2 = (const float*)d_in[4];
    const float* b2 = (const float*)d_in[5];
    float* out = (float*)d_out;

    cudaLaunchAttribute at[1];
    at[0].id = cudaLaunchAttributeProgrammaticStreamSerialization;
    at[0].val.programmaticStreamSerializationAllowed = 1;

    cudaLaunchConfig_t cfg = {};
    cfg.blockDim = dim3(256, 1, 1);
    cfg.stream = 0;

    // first kernel: plain launch (predecessor = graph start)
    k_fill<<<(N_EDGES / 2 + 255) / 256, 256>>>(ei);

    cfg.attrs = at; cfg.numAttrs = 1;

    cfg.gridDim = dim3((N_NODES * (IN_DIM / 4) + 255) / 256, 1, 1);
    cudaLaunchKernelEx(&cfg, k_xs, x, W1, W2);

    cfg.gridDim = dim3((N_NODES + 7) / 8, 1, 1);
    cudaLaunchKernelEx(&cfg, k_gather1);

    cfg.gridDim = dim3(N_PAD / 64, 1, 1);
    cudaLaunchKernelEx(&cfg, k_gemm12, b1);

    cfg.gridDim = dim3((N_NODES + 7) / 8, 1, 1);
    cudaLaunchKernelEx(&cfg, k_gather2, b2, out);
}